// round 10
// baseline (speedup 1.0000x reference)
#include <cuda_runtime.h>
#include <cuda_bf16.h>

// DenseRadiusGraph R9: single fused persistent kernel (build + search) with a
// replay-safe device-wide spin barrier. Eliminates the build kernel's serial
// 16-CTA execution and the inter-kernel launch gap (~5.5us -> ~2.5us).
//
// GRID=888 CTAs x 256 threads with __launch_bounds__(256,6): 6 CTAs/SM x 148
// SMs = 888 => all CTAs co-resident (regs capped <=40, smem trivial), so the
// grid-wide barrier cannot deadlock.
//
// Cells: x side 10 (10 cells), y/z side 20 (5 cells), 250/graph.
// Numerics (unchanged since R5): selection/ordering uses the reference's
// GEMM-form distance with plain fp32 rounding (no FMA, fixed association);
// ties broken lexicographically by (dist, index) == top_k lowest-index-first,
// independent of nondeterministic scatter order. w = direct-form, non-FMA.

#define BGR   16
#define NGR   2048
#define KNB   32
#define NCX   10
#define NCYZ  5
#define NCELL (NCX * NCYZ * NCYZ)   // 250
#define TPB   256
#define GRID  888
#define NWARP (GRID * (TPB / 32))   // 7104

// Scratch (device globals: no allocation allowed). Zero-initialized at load.
__device__ float4   g_sorted[BGR * NGR];
__device__ int      g_sidx[BGR * NGR];
__device__ int      g_cellstart[BGR * NCELL + 1];
__device__ int      g_count[BGR * NCELL];   // re-zeroed each run (phase C)
__device__ int      g_cursor[BGR * NCELL];
__device__ unsigned g_barctr;               // monotone; never reset

__device__ __forceinline__ int clamp_x(float v) {
    int c = __float2int_rd(v * 0.1f);
    return min(NCX - 1, max(0, c));
}
__device__ __forceinline__ int clamp_yz(float v) {
    int c = __float2int_rd(v * 0.05f);
    return min(NCYZ - 1, max(0, c));
}

// Replay-safe grid barrier: each use waits for the counter to reach the next
// multiple of GRID. Works across graph replays without any reset.
__device__ __forceinline__ void grid_bar() {
    __threadfence();
    __syncthreads();
    if (threadIdx.x == 0) {
        unsigned old = atomicAdd(&g_barctr, 1u);
        unsigned target = (old / GRID + 1u) * GRID;
        volatile unsigned* p = &g_barctr;
        while ((int)(*p - target) < 0) { }
    }
    __syncthreads();
    __threadfence();
}

__global__ __launch_bounds__(TPB, 6) void k_fused(
    const float* __restrict__ pos, float* __restrict__ out, int M)
{
    __shared__ int s_woff[TPB / 32];

    const int tid  = threadIdx.x;
    const int gtid = blockIdx.x * TPB + tid;
    const int warp = tid >> 5;
    const int lane = tid & 31;
    const unsigned FULL = 0xffffffffu;

    // ---- Phase A: histogram (nodes -> cells) ----------------------------
    float ax = 0.f, ay = 0.f, az = 0.f;
    int   acid = 0, ab = 0;
    const bool mine = gtid < BGR * NGR;
    if (mine) {
        ab = gtid >> 11;
        ax = pos[3 * gtid + 0];
        ay = pos[3 * gtid + 1];
        az = pos[3 * gtid + 2];
        acid = (clamp_yz(az) * NCYZ + clamp_yz(ay)) * NCX + clamp_x(ax);
        atomicAdd(&g_count[ab * NCELL + acid], 1);
    }
    grid_bar();

    // ---- Phase B: per-graph exclusive scan (CTAs 0..15) -----------------
    if (blockIdx.x < BGR) {
        const int b = blockIdx.x;
        int v = (tid < NCELL) ? g_count[b * NCELL + tid] : 0;
        int incl = v;
        #pragma unroll
        for (int d = 1; d < 32; d <<= 1) {
            int u = __shfl_up_sync(FULL, incl, d);
            if (lane >= d) incl += u;
        }
        if (lane == 31) s_woff[warp] = incl;
        __syncthreads();
        if (warp == 0 && lane < TPB / 32) {
            int w = s_woff[lane];
            int iw = w;
            #pragma unroll
            for (int d = 1; d < TPB / 32; d <<= 1) {
                int u = __shfl_up_sync(0x000000ffu, iw, d);
                if (lane >= d) iw += u;
            }
            s_woff[lane] = iw - w;   // exclusive warp offset
        }
        __syncthreads();
        if (tid < NCELL) {
            int excl = incl - v + s_woff[warp];
            g_cellstart[b * NCELL + tid] = b * NGR + excl;
            g_cursor[b * NCELL + tid]    = b * NGR + excl;
        }
        if (b == 0 && tid == 0) g_cellstart[BGR * NCELL] = BGR * NGR;
    }
    grid_bar();

    // ---- Phase C: scatter + re-zero counters for next replay ------------
    if (mine) {
        int slot = atomicAdd(&g_cursor[ab * NCELL + acid], 1);
        float sq = __fadd_rn(__fadd_rn(__fmul_rn(ax, ax), __fmul_rn(ay, ay)),
                             __fmul_rn(az, az));
        g_sorted[slot] = make_float4(ax, ay, az, sq);
        g_sidx[slot]   = gtid & (NGR - 1);
    }
    if (gtid < BGR * NCELL) g_count[gtid] = 0;
    grid_bar();

    // ---- Phase D: warp-per-query search (R8 body, warp-strided) ---------
    const int gwarp = blockIdx.x * (TPB / 32) + warp;
    const float INF = __int_as_float(0x7f800000);

    for (int q = gwarp; q < BGR * NGR; q += NWARP) {
        const int b = q >> 11;
        const int n = q & (NGR - 1);
        const float* gp = pos + (size_t)b * NGR * 3;
        float qx = gp[3 * n + 0], qy = gp[3 * n + 1], qz = gp[3 * n + 2];
        float qw = __fadd_rn(__fadd_rn(__fmul_rn(qx, qx), __fmul_rn(qy, qy)),
                             __fmul_rn(qz, qz));

        const int x0 = clamp_x(qx - 10.01f),  x1 = clamp_x(qx + 10.01f);
        const int y0 = clamp_yz(qy - 10.01f), y1 = clamp_yz(qy + 10.01f);
        const int z0 = clamp_yz(qz - 10.01f), z1 = clamp_yz(qz + 10.01f);

        float kd = INF;   // lane l holds l-th smallest (dist, idx)
        int   ki = -1;

        for (int cz = z0; cz <= z1; ++cz) {
            for (int cy = y0; cy <= y1; ++cy) {
                int rowbase = b * NCELL + (cz * NCYZ + cy) * NCX;
                int s = g_cellstart[rowbase + x0];
                int e = g_cellstart[rowbase + x1 + 1];  // contiguous x-run
                for (int t0 = s; t0 < e; t0 += 32) {
                    int  t   = t0 + lane;
                    bool act = t < e;
                    float4 c = act ? g_sorted[t]
                                   : make_float4(0.f, 0.f, 0.f, 1e30f);
                    // Reference-rounded GEMM-form d2 (no FMA, fixed assoc).
                    float m1 = __fmul_rn(qx, c.x);
                    float m2 = __fmul_rn(qy, c.y);
                    float m3 = __fmul_rn(qz, c.z);
                    float dote = __fadd_rn(__fadd_rn(m1, m2), m3);
                    float tt   = __fadd_rn(qw, c.w);
                    float d2   = __fsub_rn(tt, __fmul_rn(2.0f, dote));
                    float de = INF;
                    int   jl = n;  // self => excluded
                    if (act && d2 <= 100.001f) {
                        de = __fsqrt_rn(fmaxf(d2, 0.0f));
                        jl = g_sidx[t];
                    }
                    unsigned emask =
                        __ballot_sync(FULL, (de <= 10.0f) && (jl != n));
                    while (emask) {
                        int src = __ffs(emask) - 1;
                        emask &= emask - 1;
                        float d  = __shfl_sync(FULL, de, src);
                        int   jj = __shfl_sync(FULL, jl, src);
                        int p = __popc(__ballot_sync(FULL,
                                    (kd < d) || (kd == d && ki < jj)));
                        float sd = __shfl_up_sync(FULL, kd, 1);
                        int   si = __shfl_up_sync(FULL, ki, 1);
                        if (p < 32) {
                            if (lane == p)     { kd = d;  ki = jj; }
                            else if (lane > p) { kd = sd; ki = si; }
                        }
                    }
                }
            }
        }

        // Emit: lane l writes slot l. Invalid -> zeros.
        const long base = (long)q * KNB;
        float* rowp = out;
        float* colp = out + (long)M;
        float* wp   = out + 2L * (long)M;
        float* vp   = out + 3L * (long)M;

        float rv = 0.0f, cv = 0.0f, wv = 0.0f, vv = 0.0f;
        if (kd < INF) {
            float cxp = gp[3 * ki + 0], cyp = gp[3 * ki + 1],
                  czp = gp[3 * ki + 2];
            float dx = __fsub_rn(qx, cxp);
            float dy = __fsub_rn(qy, cyp);
            float dz = __fsub_rn(qz, czp);
            float ss = __fadd_rn(__fadd_rn(__fmul_rn(dx, dx),
                                           __fmul_rn(dy, dy)),
                                 __fmul_rn(dz, dz));
            wv = __fsqrt_rn(ss);
            rv = (float)q;
            cv = (float)(b * NGR + ki);
            vv = 1.0f;
        }
        rowp[base + lane] = rv;
        colp[base + lane] = cv;
        wp[base + lane]   = wv;
        vp[base + lane]   = vv;
    }
}

// ---- launch --------------------------------------------------------------

extern "C" void kernel_launch(void* const* d_in, const int* in_sizes, int n_in,
                              void* d_out, int out_size) {
    const float* pos = (const float*)d_in[0];
    (void)in_sizes; (void)n_in;
    float* out = (float*)d_out;
    int M = out_size / 4;

    k_fused<<<GRID, TPB>>>(pos, out, M);
}